// round 3
// baseline (speedup 1.0000x reference)
#include <cuda_runtime.h>
#include <stdint.h>

#define BATCH   16
#define NANCH   261888          // 3 * (65536+16384+4096+1024+256)
#define TOPK    1000
#define CAP     4096            // candidate capacity per image (expected ~1300 max)
#define NBINS   65536
#define NLEV    5

// ---- static level tables -------------------------------------------------
__constant__ int   c_HW[NLEV]     = {65536, 16384, 4096, 1024, 256};
__constant__ int   c_W[NLEV]      = {256, 128, 64, 32, 16};
__constant__ float c_stride[NLEV] = {4.f, 8.f, 16.f, 32.f, 64.f};
__constant__ float c_size[NLEV]   = {32.f, 64.f, 128.f, 256.f, 512.f};
__constant__ int   c_off[NLEV]    = {0, 196608, 245760, 258048, 261120};

__device__ __forceinline__ int level_of(int j, int& rem) {
    if (j < 196608) { rem = j;          return 0; }
    if (j < 245760) { rem = j - 196608; return 1; }
    if (j < 258048) { rem = j - 245760; return 2; }
    if (j < 261120) { rem = j - 258048; return 3; }
    rem = j - 261120; return 4;
}

// ---- scratch (static device globals; no allocation anywhere) -------------
static __device__ unsigned int       g_hist[BATCH * NBINS];
static __device__ unsigned int       g_thr16[BATCH];
static __device__ unsigned int       g_cnt[BATCH];
static __device__ unsigned long long g_cand[BATCH * CAP];
static __device__ unsigned int       g_selA[BATCH * TOPK];
static __device__ unsigned int       g_selU[BATCH * TOPK];
static __device__ float g_cx[BATCH*TOPK], g_cy[BATCH*TOPK], g_w[BATCH*TOPK], g_h[BATCH*TOPK];
static __device__ float g_sc[BATCH*TOPK];
static __device__ float g_bx1[BATCH*TOPK], g_by1[BATCH*TOPK], g_bx2[BATCH*TOPK], g_by2[BATCH*TOPK];
static __device__ float g_ar[BATCH*TOPK];
static __device__ unsigned int       g_mask[BATCH * TOPK * 32];
static __device__ unsigned int       g_keepw[BATCH * 32];

// precise sigmoid matching XLA logistic expansion: 1 / (1 + exp(-x))
__device__ __forceinline__ float sigmoid_precise(float x) {
    return __fdiv_rn(1.0f, __fadd_rn(1.0f, expf(-x)));
}

// ---- K1: sigmoid -> 16-bit histogram only (no key store) -----------------
__global__ void k_keys(const float* __restrict__ c0, const float* __restrict__ c1,
                       const float* __restrict__ c2, const float* __restrict__ c3,
                       const float* __restrict__ c4) {
    int idx = blockIdx.x * 256 + threadIdx.x;
    if (idx >= BATCH * NANCH) return;
    int b = idx / NANCH, j = idx - b * NANCH;
    int rem; int lev = level_of(j, rem);
    const float* p = (lev == 0) ? c0 : (lev == 1) ? c1 : (lev == 2) ? c2 : (lev == 3) ? c3 : c4;
    float x = p[(size_t)b * 3 * c_HW[lev] + rem];      // channel-major: coalesced
    unsigned u = __float_as_uint(sigmoid_precise(x));  // score in (0,1): bit-order == value-order
    atomicAdd(&g_hist[b * NBINS + (u >> 16)], 1u);
}

// ---- K2: fully parallel per-image 16-bit threshold -----------------------
// thr = max t with count(u>>16 >= t) >= TOPK
__global__ void k_thr() {
    __shared__ unsigned s_sum[1024];
    __shared__ unsigned s_val[1024];
    __shared__ int s_chunk;
    __shared__ unsigned s_above;
    __shared__ unsigned s_bin[64];
    int b = blockIdx.x, t = threadIdx.x;   // 1024 threads
    const unsigned* h = g_hist + b * NBINS;
    // chunk sums: thread t owns bins [t*64, t*64+64)
    unsigned s = 0;
    int base = t * 64;
#pragma unroll 8
    for (int i = 0; i < 64; i++) s += h[base + i];
    s_sum[t] = s;
    __syncthreads();
    // inclusive suffix scan over chunks (Hillis-Steele)
    unsigned v = s;
    for (int off = 1; off < 1024; off <<= 1) {
        s_val[t] = v;
        __syncthreads();
        unsigned add = (t + off < 1024) ? s_val[t + off] : 0u;
        __syncthreads();
        v += add;
    }
    s_val[t] = v;
    __syncthreads();
    // crossing chunk c: suffix_incl[c] >= TOPK && suffix_incl[c+1] < TOPK
    if (v >= TOPK && (t == 1023 || s_val[t + 1] < TOPK)) {
        s_chunk = t;
        s_above = (t == 1023) ? 0u : s_val[t + 1];
    }
    __syncthreads();
    int c = s_chunk;
    unsigned above = s_above;   // count strictly above chunk c
    if (t < 64) s_bin[t] = h[c * 64 + t];
    __syncthreads();
    if (t < 64) {
        unsigned suf = 0;
        for (int j = 63; j >= t; j--) suf += s_bin[j];
        unsigned sufnext = suf - s_bin[t];
        if (above + suf >= TOPK && above + sufnext < TOPK)
            g_thr16[b] = (unsigned)(c * 64 + t);
    }
}

// ---- K3: compact candidates (key64 = score_bits<<32 | ~anchor_index) -----
__global__ void k_compact(const float* __restrict__ c0, const float* __restrict__ c1,
                          const float* __restrict__ c2, const float* __restrict__ c3,
                          const float* __restrict__ c4) {
    int idx = blockIdx.x * 256 + threadIdx.x;
    if (idx >= BATCH * NANCH) return;
    int b = idx / NANCH, j = idx - b * NANCH;
    int rem; int lev = level_of(j, rem);
    const float* p = (lev == 0) ? c0 : (lev == 1) ? c1 : (lev == 2) ? c2 : (lev == 3) ? c3 : c4;
    float x = p[(size_t)b * 3 * c_HW[lev] + rem];
    unsigned u = __float_as_uint(sigmoid_precise(x));
    if ((u >> 16) >= __ldg(&g_thr16[b])) {
        int HW = c_HW[lev];
        int k = rem / HW, cell = rem - k * HW;
        unsigned a = (unsigned)(c_off[lev] + cell * 3 + k);
        unsigned pos = atomicAdd(&g_cnt[b], 1u);
        if (pos < CAP)
            g_cand[b * CAP + pos] =
                ((unsigned long long)u << 32) | (unsigned long long)(0xFFFFFFFFu - a);
    }
}

// ---- K4: exact rank of each candidate == stable sort position ------------
__global__ void k_rank() {
    __shared__ unsigned long long sk[CAP];   // 32 KB
    int b = blockIdx.x, t = threadIdx.x;     // 1024 threads
    unsigned n = g_cnt[b]; if (n > CAP) n = CAP;
    for (int i = t; i < (int)n; i += 1024) sk[i] = g_cand[b * CAP + i];
    __syncthreads();
    unsigned long long k0 = (t            < (int)n) ? sk[t]        : ~0ull;
    unsigned long long k1 = (t + 1024     < (int)n) ? sk[t + 1024] : ~0ull;
    unsigned long long k2 = (t + 2048     < (int)n) ? sk[t + 2048] : ~0ull;
    unsigned long long k3 = (t + 3072     < (int)n) ? sk[t + 3072] : ~0ull;
    unsigned r0 = 0, r1 = 0, r2 = 0, r3 = 0;
    for (int j = 0; j < (int)n; j++) {
        unsigned long long v = sk[j];      // broadcast
        r0 += (v > k0); r1 += (v > k1); r2 += (v > k2); r3 += (v > k3);
    }
#define EMIT(kk, rr, ii)                                                          \
    if ((ii) < (int)n && (rr) < TOPK) {                                           \
        g_selU[b * TOPK + (rr)] = (unsigned)((kk) >> 32);                         \
        g_selA[b * TOPK + (rr)] = 0xFFFFFFFFu - (unsigned)((kk) & 0xFFFFFFFFull); \
    }
    EMIT(k0, r0, t); EMIT(k1, r1, t + 1024); EMIT(k2, r2, t + 2048); EMIT(k3, r3, t + 3072);
#undef EMIT
}

// ---- K5: decode the selected 16x1000 boxes -------------------------------
__global__ void k_decode(const float* __restrict__ b0, const float* __restrict__ b1,
                         const float* __restrict__ b2, const float* __restrict__ b3,
                         const float* __restrict__ b4) {
    int i = blockIdx.x * 256 + threadIdx.x;
    if (i >= BATCH * TOPK) return;
    int b = i / TOPK;
    int a = (int)g_selA[i];
    float score = __uint_as_float(g_selU[i]);
    int rem; int lev = level_of(a, rem);
    int cell = rem / 3, k = rem - cell * 3;
    int W = c_W[lev], HW = c_HW[lev];
    int hh = cell / W, ww = cell - hh * W;
    float st = c_stride[lev], sz = c_size[lev];
    float acx = ((float)ww + 0.5f) * st;
    float acy = ((float)hh + 0.5f) * st;
    float ratio = (k == 0) ? 0.5f : (k == 1) ? 1.0f : 2.0f;
    float sr = __fsqrt_rn(ratio);
    float aw = __fdiv_rn(sz, sr);
    float ah = sz * sr;
    const float* bp = (lev == 0) ? b0 : (lev == 1) ? b1 : (lev == 2) ? b2 : (lev == 3) ? b3 : b4;
    size_t base = (size_t)b * 12 * HW + (size_t)k * 4 * HW + cell;
    float d0 = bp[base], d1 = bp[base + HW], d2 = bp[base + 2 * (size_t)HW], d3 = bp[base + 3 * (size_t)HW];
    float cx = acx + d0 * aw;
    float cy = acy + d1 * ah;
    float w  = aw * expf(fminf(fmaxf(d2, -4.0f), 4.0f));
    float h  = ah * expf(fminf(fmaxf(d3, -4.0f), 4.0f));
    g_cx[i] = cx; g_cy[i] = cy; g_w[i] = w; g_h[i] = h; g_sc[i] = score;
    float x1 = cx - w * 0.5f, y1 = cy - h * 0.5f;
    float x2 = cx + w * 0.5f, y2 = cy + h * 0.5f;
    g_bx1[i] = x1; g_by1[i] = y1; g_bx2[i] = x2; g_by2[i] = y2;
    g_ar[i] = (x2 - x1) * (y2 - y1);
}

// ---- K6: NMS pairwise suppression bitmask (rows i, 32 words of j-bits) ---
__global__ void k_mask() {
    __shared__ float sx1[TOPK], sy1[TOPK], sx2[TOPK], sy2[TOPK], sar[TOPK];
    int b = blockIdx.y;
    int tid = threadIdx.y * 32 + threadIdx.x;
    for (int i = tid; i < TOPK; i += 1024) {
        int g = b * TOPK + i;
        sx1[i] = g_bx1[g]; sy1[i] = g_by1[g];
        sx2[i] = g_bx2[g]; sy2[i] = g_by2[g];
        sar[i] = g_ar[g];
    }
    __syncthreads();
    int i = blockIdx.x * 32 + threadIdx.y;
    if (i < TOPK) {
        float x1 = sx1[i], y1 = sy1[i], x2 = sx2[i], y2 = sy2[i], ar = sar[i];
        unsigned bits = 0;
        int j0 = threadIdx.x * 32;
#pragma unroll 4
        for (int jj = 0; jj < 32; jj++) {
            int j = j0 + jj;
            if (j < TOPK && j > i) {
                float iw = fmaxf(fminf(x2, sx2[j]) - fmaxf(x1, sx1[j]), 0.0f);
                float ih = fmaxf(fminf(y2, sy2[j]) - fmaxf(y1, sy1[j]), 0.0f);
                float inter = iw * ih;
                float iou = inter / (ar + sar[j] - inter + 1e-6f);
                if (iou > 0.7f) bits |= (1u << jj);
            }
        }
        g_mask[((size_t)b * TOPK + i) * 32 + threadIdx.x] = bits;
    }
}

// ---- K7: greedy NMS reduce — static-mask prefetch, ALU-only serial chain -
__global__ void k_reduce() {
    int b = blockIdx.x, lane = threadIdx.x;   // 32 threads (one warp)
    const unsigned* m = g_mask + (size_t)b * TOPK * 32;
    unsigned remv = 0;                        // lane l holds suppressed-bits of boxes [32l,32l+31]
#pragma unroll 1
    for (int w = 0; w < 32; w++) {
        int rows = TOPK - w * 32; if (rows > 32) rows = 32;
        unsigned cur = __shfl_sync(0xffffffffu, remv, w);
        unsigned mw_[32], mc_[32];
#pragma unroll
        for (int r = 0; r < 32; r++) {
            int i = w * 32 + r;
            bool vld = (r < rows);
            mw_[r] = vld ? m[(size_t)i * 32 + w]    : 0u;  // broadcast load
            mc_[r] = vld ? m[(size_t)i * 32 + lane] : 0u;  // per-lane column word
        }
        unsigned newremv = 0;
#pragma unroll
        for (int r = 0; r < 32; r++) {
            if (!((cur >> r) & 1u)) {   // box kept
                cur     |= mw_[r];      // intra-word forward suppression (mask has only j>i bits)
                newremv |= mc_[r];
            }
        }
        remv |= newremv;
    }
    g_keepw[b * 32 + lane] = ~remv;
}

// ---- K8: scatter kept boxes (+score) and keep mask into zeroed output ----
__global__ void k_scatter(float* __restrict__ out, float* __restrict__ keepF) {
    int i = blockIdx.x * 256 + threadIdx.x;
    if (i >= BATCH * TOPK) return;
    int b = i / TOPK, t = i - b * TOPK;
    if (!((g_keepw[b * 32 + (t >> 5)] >> (t & 31)) & 1u)) return;
    size_t base = (size_t)b * NANCH + g_selA[i];
    float* o = out + base * 5;
    o[0] = g_cx[i]; o[1] = g_cy[i]; o[2] = g_w[i]; o[3] = g_h[i]; o[4] = g_sc[i];
    if (keepF) keepF[base] = 1.0f;
}

// ---- launch --------------------------------------------------------------
extern "C" void kernel_launch(void* const* d_in, const int* in_sizes, int n_in,
                              void* d_out, int out_size) {
    if (n_in < 10) return;
    const float* cls[5]; const float* bbx[5];
    if (in_sizes[1] == 786432) {     // grouped: cls_p2..p6, bbox_p2..p6
        for (int l = 0; l < 5; l++) { cls[l] = (const float*)d_in[l]; bbx[l] = (const float*)d_in[5 + l]; }
    } else {                         // interleaved
        for (int l = 0; l < 5; l++) { cls[l] = (const float*)d_in[2 * l]; bbx[l] = (const float*)d_in[2 * l + 1]; }
    }

    void* pHist = nullptr; void* pCnt = nullptr;
    cudaGetSymbolAddress(&pHist, g_hist);
    cudaGetSymbolAddress(&pCnt,  g_cnt);
    cudaMemsetAsync(pHist, 0, sizeof(unsigned) * BATCH * NBINS, 0);
    cudaMemsetAsync(pCnt,  0, sizeof(unsigned) * BATCH, 0);
    cudaMemsetAsync(d_out, 0, (size_t)out_size * sizeof(float), 0);

    const long long BA = (long long)BATCH * NANCH;
    float* keepF = nullptr;
    if ((long long)out_size >= BA * 6) keepF = (float*)d_out + BA * 5;

    int nba = (BATCH * NANCH + 255) / 256;   // 16368
    k_keys<<<nba, 256>>>(cls[0], cls[1], cls[2], cls[3], cls[4]);
    k_thr<<<BATCH, 1024>>>();
    k_compact<<<nba, 256>>>(cls[0], cls[1], cls[2], cls[3], cls[4]);
    k_rank<<<BATCH, 1024>>>();
    k_decode<<<(BATCH * TOPK + 255) / 256, 256>>>(bbx[0], bbx[1], bbx[2], bbx[3], bbx[4]);
    k_mask<<<dim3((TOPK + 31) / 32, BATCH), dim3(32, 32)>>>();
    k_reduce<<<BATCH, 32>>>();
    k_scatter<<<(BATCH * TOPK + 255) / 256, 256>>>((float*)d_out, keepF);
}

// round 4
// speedup vs baseline: 1.1502x; 1.1502x over previous
#include <cuda_runtime.h>
#include <stdint.h>

#define BATCH   16
#define NANCH   261888          // 3 * (65536+16384+4096+1024+256)
#define TOPK    1000
#define CAP     4096            // candidate capacity per image (expected ~1300 max)
#define NBINS   65536
#define NLEV    5
#define RCHUNK  256             // k_rank rows per block

// ---- static level tables -------------------------------------------------
__constant__ int   c_HW[NLEV]     = {65536, 16384, 4096, 1024, 256};
__constant__ int   c_W[NLEV]      = {256, 128, 64, 32, 16};
__constant__ float c_stride[NLEV] = {4.f, 8.f, 16.f, 32.f, 64.f};
__constant__ float c_size[NLEV]   = {32.f, 64.f, 128.f, 256.f, 512.f};
__constant__ int   c_off[NLEV]    = {0, 196608, 245760, 258048, 261120};

__device__ __forceinline__ int level_of(int j, int& rem) {
    if (j < 196608) { rem = j;          return 0; }
    if (j < 245760) { rem = j - 196608; return 1; }
    if (j < 258048) { rem = j - 245760; return 2; }
    if (j < 261120) { rem = j - 258048; return 3; }
    rem = j - 261120; return 4;
}

// ---- scratch (static device globals; no allocation anywhere) -------------
static __device__ unsigned int       g_hist[BATCH * NBINS];
static __device__ unsigned int       g_thr16[BATCH];
static __device__ unsigned int       g_cnt[BATCH];
static __device__ unsigned long long g_cand[BATCH * CAP];
static __device__ unsigned int       g_selA[BATCH * TOPK];
static __device__ unsigned int       g_selU[BATCH * TOPK];
static __device__ float g_cx[BATCH*TOPK], g_cy[BATCH*TOPK], g_w[BATCH*TOPK], g_h[BATCH*TOPK];
static __device__ float g_sc[BATCH*TOPK];
static __device__ float g_bx1[BATCH*TOPK], g_by1[BATCH*TOPK], g_bx2[BATCH*TOPK], g_by2[BATCH*TOPK];
static __device__ float g_ar[BATCH*TOPK];
static __device__ unsigned int       g_mask[BATCH * TOPK * 32];
static __device__ unsigned int       g_keepw[BATCH * 32];

// precise sigmoid matching XLA logistic expansion: 1 / (1 + exp(-x))
__device__ __forceinline__ float sigmoid_precise(float x) {
    return __fdiv_rn(1.0f, __fadd_rn(1.0f, expf(-x)));
}

// ---- K1: sigmoid -> 16-bit histogram only (no key store) -----------------
__global__ void k_keys(const float* __restrict__ c0, const float* __restrict__ c1,
                       const float* __restrict__ c2, const float* __restrict__ c3,
                       const float* __restrict__ c4) {
    int idx = blockIdx.x * 256 + threadIdx.x;
    if (idx >= BATCH * NANCH) return;
    int b = idx / NANCH, j = idx - b * NANCH;
    int rem; int lev = level_of(j, rem);
    const float* p = (lev == 0) ? c0 : (lev == 1) ? c1 : (lev == 2) ? c2 : (lev == 3) ? c3 : c4;
    float x = p[(size_t)b * 3 * c_HW[lev] + rem];      // channel-major: coalesced
    unsigned u = __float_as_uint(sigmoid_precise(x));  // score in (0,1): bit-order == value-order
    atomicAdd(&g_hist[b * NBINS + (u >> 16)], 1u);
}

// ---- K2: fully parallel per-image 16-bit threshold -----------------------
// thr = max t with count(u>>16 >= t) >= TOPK
__global__ void k_thr() {
    __shared__ unsigned s_sum[1024];
    __shared__ unsigned s_val[1024];
    __shared__ int s_chunk;
    __shared__ unsigned s_above;
    __shared__ unsigned s_bin[64];
    int b = blockIdx.x, t = threadIdx.x;   // 1024 threads
    const unsigned* h = g_hist + b * NBINS;
    unsigned s = 0;
    int base = t * 64;
#pragma unroll 8
    for (int i = 0; i < 64; i++) s += h[base + i];
    s_sum[t] = s;
    __syncthreads();
    unsigned v = s;
    for (int off = 1; off < 1024; off <<= 1) {
        s_val[t] = v;
        __syncthreads();
        unsigned add = (t + off < 1024) ? s_val[t + off] : 0u;
        __syncthreads();
        v += add;
    }
    s_val[t] = v;
    __syncthreads();
    if (v >= TOPK && (t == 1023 || s_val[t + 1] < TOPK)) {
        s_chunk = t;
        s_above = (t == 1023) ? 0u : s_val[t + 1];
    }
    __syncthreads();
    int c = s_chunk;
    unsigned above = s_above;
    if (t < 64) s_bin[t] = h[c * 64 + t];
    __syncthreads();
    if (t < 64) {
        unsigned suf = 0;
        for (int j = 63; j >= t; j--) suf += s_bin[j];
        unsigned sufnext = suf - s_bin[t];
        if (above + suf >= TOPK && above + sufnext < TOPK)
            g_thr16[b] = (unsigned)(c * 64 + t);
    }
}

// ---- K3: compact candidates (key64 = score_bits<<32 | ~anchor_index) -----
__global__ void k_compact(const float* __restrict__ c0, const float* __restrict__ c1,
                          const float* __restrict__ c2, const float* __restrict__ c3,
                          const float* __restrict__ c4) {
    int idx = blockIdx.x * 256 + threadIdx.x;
    if (idx >= BATCH * NANCH) return;
    int b = idx / NANCH, j = idx - b * NANCH;
    int rem; int lev = level_of(j, rem);
    const float* p = (lev == 0) ? c0 : (lev == 1) ? c1 : (lev == 2) ? c2 : (lev == 3) ? c3 : c4;
    float x = p[(size_t)b * 3 * c_HW[lev] + rem];
    unsigned u = __float_as_uint(sigmoid_precise(x));
    if ((u >> 16) >= __ldg(&g_thr16[b])) {
        int HW = c_HW[lev];
        int k = rem / HW, cell = rem - k * HW;
        unsigned a = (unsigned)(c_off[lev] + cell * 3 + k);
        unsigned pos = atomicAdd(&g_cnt[b], 1u);
        if (pos < CAP)
            g_cand[b * CAP + pos] =
                ((unsigned long long)u << 32) | (unsigned long long)(0xFFFFFFFFu - a);
    }
}

// ---- K4: exact rank of each candidate == stable sort position ------------
// grid (CAP/RCHUNK, BATCH), block RCHUNK; inactive chunks exit early
__global__ void k_rank() {
    __shared__ unsigned long long sk[CAP];   // 32 KB (only first n used)
    int b = blockIdx.y;
    unsigned n = g_cnt[b]; if (n > CAP) n = CAP;
    int i0 = blockIdx.x * RCHUNK;
    if (i0 >= (int)n) return;                // uniform per block
    for (int i = threadIdx.x; i < (int)n; i += RCHUNK) sk[i] = g_cand[b * CAP + i];
    __syncthreads();
    int i = i0 + threadIdx.x;
    unsigned long long key = (i < (int)n) ? sk[i] : ~0ull;
    unsigned r = 0;
#pragma unroll 4
    for (int j = 0; j < (int)n; j++) r += (sk[j] > key);
    if (i < (int)n && r < TOPK) {
        g_selU[b * TOPK + r] = (unsigned)(key >> 32);
        g_selA[b * TOPK + r] = 0xFFFFFFFFu - (unsigned)(key & 0xFFFFFFFFull);
    }
}

// ---- K5: decode the selected 16x1000 boxes -------------------------------
__global__ void k_decode(const float* __restrict__ b0, const float* __restrict__ b1,
                         const float* __restrict__ b2, const float* __restrict__ b3,
                         const float* __restrict__ b4) {
    int i = blockIdx.x * 256 + threadIdx.x;
    if (i >= BATCH * TOPK) return;
    int b = i / TOPK;
    int a = (int)g_selA[i];
    float score = __uint_as_float(g_selU[i]);
    int rem; int lev = level_of(a, rem);
    int cell = rem / 3, k = rem - cell * 3;
    int W = c_W[lev], HW = c_HW[lev];
    int hh = cell / W, ww = cell - hh * W;
    float st = c_stride[lev], sz = c_size[lev];
    float acx = ((float)ww + 0.5f) * st;
    float acy = ((float)hh + 0.5f) * st;
    float ratio = (k == 0) ? 0.5f : (k == 1) ? 1.0f : 2.0f;
    float sr = __fsqrt_rn(ratio);
    float aw = __fdiv_rn(sz, sr);
    float ah = sz * sr;
    const float* bp = (lev == 0) ? b0 : (lev == 1) ? b1 : (lev == 2) ? b2 : (lev == 3) ? b3 : b4;
    size_t base = (size_t)b * 12 * HW + (size_t)k * 4 * HW + cell;
    float d0 = bp[base], d1 = bp[base + HW], d2 = bp[base + 2 * (size_t)HW], d3 = bp[base + 3 * (size_t)HW];
    float cx = acx + d0 * aw;
    float cy = acy + d1 * ah;
    float w  = aw * expf(fminf(fmaxf(d2, -4.0f), 4.0f));
    float h  = ah * expf(fminf(fmaxf(d3, -4.0f), 4.0f));
    g_cx[i] = cx; g_cy[i] = cy; g_w[i] = w; g_h[i] = h; g_sc[i] = score;
    float x1 = cx - w * 0.5f, y1 = cy - h * 0.5f;
    float x2 = cx + w * 0.5f, y2 = cy + h * 0.5f;
    g_bx1[i] = x1; g_by1[i] = y1; g_bx2[i] = x2; g_by2[i] = y2;
    g_ar[i] = (x2 - x1) * (y2 - y1);
}

// ---- K6: NMS suppression bitmask — broadcast pattern (conflict-free) -----
// grid ((TOPK+127)/128, BATCH), block 128. Thread owns row i; inner loop over
// j with ALL lanes reading the same smem word (broadcast, no bank conflicts).
__global__ void k_mask() {
    __shared__ float sx1[TOPK], sy1[TOPK], sx2[TOPK], sy2[TOPK], sar[TOPK];
    int b = blockIdx.y;
    for (int i = threadIdx.x; i < TOPK; i += 128) {
        int g = b * TOPK + i;
        sx1[i] = g_bx1[g]; sy1[i] = g_by1[g];
        sx2[i] = g_bx2[g]; sy2[i] = g_by2[g];
        sar[i] = g_ar[g];
    }
    __syncthreads();
    int i = blockIdx.x * 128 + threadIdx.x;
    if (i >= TOPK) return;
    float x1 = sx1[i], y1 = sy1[i], x2 = sx2[i], y2 = sy2[i], ar = sar[i];
    unsigned* out = &g_mask[((size_t)b * TOPK + i) * 32];
    int w0 = i >> 5;
    for (int w = 0; w < w0; w++) out[w] = 0u;   // must clear: buffer stale across replays
    for (int w = w0; w < 32; w++) {
        unsigned bits = 0;
#pragma unroll
        for (int jj = 0; jj < 32; jj++) {
            int j = w * 32 + jj;
            if (j > i && j < TOPK) {
                float iw = fmaxf(fminf(x2, sx2[j]) - fmaxf(x1, sx1[j]), 0.0f);
                float ih = fmaxf(fminf(y2, sy2[j]) - fmaxf(y1, sy1[j]), 0.0f);
                float inter = iw * ih;
                float iou = inter / (ar + sar[j] - inter + 1e-6f);
                if (iou > 0.7f) bits |= (1u << jj);
            }
        }
        out[w] = bits;
    }
}

// ---- K7: greedy NMS reduce — static-mask prefetch, ALU-only serial chain -
__global__ void k_reduce() {
    int b = blockIdx.x, lane = threadIdx.x;   // 32 threads (one warp)
    const unsigned* m = g_mask + (size_t)b * TOPK * 32;
    unsigned remv = 0;                        // lane l holds suppressed-bits of boxes [32l,32l+31]
#pragma unroll 1
    for (int w = 0; w < 32; w++) {
        int rows = TOPK - w * 32; if (rows > 32) rows = 32;
        unsigned cur = __shfl_sync(0xffffffffu, remv, w);
        unsigned mw_[32], mc_[32];
#pragma unroll
        for (int r = 0; r < 32; r++) {
            int i = w * 32 + r;
            bool vld = (r < rows);
            mw_[r] = vld ? m[(size_t)i * 32 + w]    : 0u;  // diagonal word (broadcast)
            mc_[r] = vld ? m[(size_t)i * 32 + lane] : 0u;  // per-lane column word
        }
        unsigned newremv = 0;
#pragma unroll
        for (int r = 0; r < 32; r++) {
            if (!((cur >> r) & 1u)) {   // box kept
                cur     |= mw_[r];      // intra-word forward suppression (mask has only j>i bits)
                newremv |= mc_[r];
            }
        }
        remv |= newremv;
    }
    g_keepw[b * 32 + lane] = ~remv;
}

// ---- K8: scatter kept boxes (+score) and keep mask into zeroed output ----
__global__ void k_scatter(float* __restrict__ out, float* __restrict__ keepF) {
    int i = blockIdx.x * 256 + threadIdx.x;
    if (i >= BATCH * TOPK) return;
    int b = i / TOPK, t = i - b * TOPK;
    if (!((g_keepw[b * 32 + (t >> 5)] >> (t & 31)) & 1u)) return;
    size_t base = (size_t)b * NANCH + g_selA[i];
    float* o = out + base * 5;
    o[0] = g_cx[i]; o[1] = g_cy[i]; o[2] = g_w[i]; o[3] = g_h[i]; o[4] = g_sc[i];
    if (keepF) keepF[base] = 1.0f;
}

// ---- launch --------------------------------------------------------------
extern "C" void kernel_launch(void* const* d_in, const int* in_sizes, int n_in,
                              void* d_out, int out_size) {
    if (n_in < 10) return;
    const float* cls[5]; const float* bbx[5];
    if (in_sizes[1] == 786432) {     // grouped: cls_p2..p6, bbox_p2..p6
        for (int l = 0; l < 5; l++) { cls[l] = (const float*)d_in[l]; bbx[l] = (const float*)d_in[5 + l]; }
    } else {                         // interleaved
        for (int l = 0; l < 5; l++) { cls[l] = (const float*)d_in[2 * l]; bbx[l] = (const float*)d_in[2 * l + 1]; }
    }

    void* pHist = nullptr; void* pCnt = nullptr;
    cudaGetSymbolAddress(&pHist, g_hist);
    cudaGetSymbolAddress(&pCnt,  g_cnt);
    cudaMemsetAsync(pHist, 0, sizeof(unsigned) * BATCH * NBINS, 0);
    cudaMemsetAsync(pCnt,  0, sizeof(unsigned) * BATCH, 0);
    cudaMemsetAsync(d_out, 0, (size_t)out_size * sizeof(float), 0);

    const long long BA = (long long)BATCH * NANCH;
    float* keepF = nullptr;
    if ((long long)out_size >= BA * 6) keepF = (float*)d_out + BA * 5;

    int nba = (BATCH * NANCH + 255) / 256;   // 16368
    k_keys<<<nba, 256>>>(cls[0], cls[1], cls[2], cls[3], cls[4]);
    k_thr<<<BATCH, 1024>>>();
    k_compact<<<nba, 256>>>(cls[0], cls[1], cls[2], cls[3], cls[4]);
    k_rank<<<dim3(CAP / RCHUNK, BATCH), RCHUNK>>>();
    k_decode<<<(BATCH * TOPK + 255) / 256, 256>>>(bbx[0], bbx[1], bbx[2], bbx[3], bbx[4]);
    k_mask<<<dim3((TOPK + 127) / 128, BATCH), 128>>>();
    k_reduce<<<BATCH, 32>>>();
    k_scatter<<<(BATCH * TOPK + 255) / 256, 256>>>((float*)d_out, keepF);
}

// round 5
// speedup vs baseline: 1.5810x; 1.3745x over previous
#include <cuda_runtime.h>
#include <stdint.h>

#define BATCH   16
#define NANCH   261888          // 3 * (65536+16384+4096+1024+256)
#define TOPK    1000
#define CAP     4096            // candidate capacity per image (expected ~1300 max)
#define NBINS   65536
#define NLEV    5
#define RCHUNK  256             // k_rank rows per block

// ---- static level tables -------------------------------------------------
__constant__ int   c_HW[NLEV]     = {65536, 16384, 4096, 1024, 256};
__constant__ int   c_W[NLEV]      = {256, 128, 64, 32, 16};
__constant__ float c_stride[NLEV] = {4.f, 8.f, 16.f, 32.f, 64.f};
__constant__ float c_size[NLEV]   = {32.f, 64.f, 128.f, 256.f, 512.f};
__constant__ int   c_off[NLEV]    = {0, 196608, 245760, 258048, 261120};

__device__ __forceinline__ int level_of(int j, int& rem) {
    if (j < 196608) { rem = j;          return 0; }
    if (j < 245760) { rem = j - 196608; return 1; }
    if (j < 258048) { rem = j - 245760; return 2; }
    if (j < 261120) { rem = j - 258048; return 3; }
    rem = j - 261120; return 4;
}

// ---- scratch (static device globals; no allocation anywhere) -------------
struct Scratch { unsigned hist[BATCH * NBINS]; unsigned cnt[BATCH]; };
static __device__ Scratch            g_s;          // zeroed by ONE memset
static __device__ unsigned int       g_thr16[BATCH];
static __device__ unsigned long long g_cand[BATCH * CAP];
static __device__ unsigned int       g_selA[BATCH * TOPK];
static __device__ unsigned int       g_selU[BATCH * TOPK];
static __device__ float g_cx[BATCH*TOPK], g_cy[BATCH*TOPK], g_w[BATCH*TOPK], g_h[BATCH*TOPK];
static __device__ float g_sc[BATCH*TOPK];
static __device__ float g_bx1[BATCH*TOPK], g_by1[BATCH*TOPK], g_bx2[BATCH*TOPK], g_by2[BATCH*TOPK];
static __device__ float g_ar[BATCH*TOPK];
static __device__ unsigned int       g_mask[BATCH * TOPK * 32];

// precise sigmoid matching XLA logistic expansion: 1 / (1 + exp(-x))
__device__ __forceinline__ float sigmoid_precise(float x) {
    return __fdiv_rn(1.0f, __fadd_rn(1.0f, expf(-x)));
}

// ---- dummy: shifts the ncu capture slot onto k_keys/k_compact ------------
__global__ void k_nop() {}

// ---- K1: sigmoid -> 16-bit histogram only --------------------------------
__global__ void k_keys(const float* __restrict__ c0, const float* __restrict__ c1,
                       const float* __restrict__ c2, const float* __restrict__ c3,
                       const float* __restrict__ c4) {
    int idx = blockIdx.x * 256 + threadIdx.x;
    if (idx >= BATCH * NANCH) return;
    int b = idx / NANCH, j = idx - b * NANCH;
    int rem; int lev = level_of(j, rem);
    const float* p = (lev == 0) ? c0 : (lev == 1) ? c1 : (lev == 2) ? c2 : (lev == 3) ? c3 : c4;
    float x = p[(size_t)b * 3 * c_HW[lev] + rem];      // channel-major: coalesced
    unsigned u = __float_as_uint(sigmoid_precise(x));  // score in (0,1): bit-order == value-order
    atomicAdd(&g_s.hist[b * NBINS + (u >> 16)], 1u);
}

// ---- K2: fully parallel per-image 16-bit threshold -----------------------
// thr = max t with count(u>>16 >= t) >= TOPK
__global__ void k_thr() {
    __shared__ unsigned s_sum[1024];
    __shared__ unsigned s_val[1024];
    __shared__ int s_chunk;
    __shared__ unsigned s_above;
    __shared__ unsigned s_bin[64];
    int b = blockIdx.x, t = threadIdx.x;   // 1024 threads
    const unsigned* h = g_s.hist + b * NBINS;
    const uint4* h4 = (const uint4*)h;
    unsigned s = 0;
    int base4 = t * 16;                     // bins [t*64, t*64+64) as 16 uint4
#pragma unroll 4
    for (int i = 0; i < 16; i++) {
        uint4 v4 = h4[base4 + i];
        s += v4.x + v4.y + v4.z + v4.w;
    }
    s_sum[t] = s;
    __syncthreads();
    unsigned v = s;
    for (int off = 1; off < 1024; off <<= 1) {
        s_val[t] = v;
        __syncthreads();
        unsigned add = (t + off < 1024) ? s_val[t + off] : 0u;
        __syncthreads();
        v += add;
    }
    s_val[t] = v;
    __syncthreads();
    if (v >= TOPK && (t == 1023 || s_val[t + 1] < TOPK)) {
        s_chunk = t;
        s_above = (t == 1023) ? 0u : s_val[t + 1];
    }
    __syncthreads();
    int c = s_chunk;
    unsigned above = s_above;
    if (t < 64) s_bin[t] = h[c * 64 + t];
    __syncthreads();
    if (t < 64) {
        unsigned suf = 0;
        for (int j = 63; j >= t; j--) suf += s_bin[j];
        unsigned sufnext = suf - s_bin[t];
        if (above + suf >= TOPK && above + sufnext < TOPK)
            g_thr16[b] = (unsigned)(c * 64 + t);
    }
}

// ---- K3: compact candidates (key64 = score_bits<<32 | ~anchor_index) -----
__global__ void k_compact(const float* __restrict__ c0, const float* __restrict__ c1,
                          const float* __restrict__ c2, const float* __restrict__ c3,
                          const float* __restrict__ c4) {
    int idx = blockIdx.x * 256 + threadIdx.x;
    if (idx >= BATCH * NANCH) return;
    int b = idx / NANCH, j = idx - b * NANCH;
    int rem; int lev = level_of(j, rem);
    const float* p = (lev == 0) ? c0 : (lev == 1) ? c1 : (lev == 2) ? c2 : (lev == 3) ? c3 : c4;
    float x = p[(size_t)b * 3 * c_HW[lev] + rem];
    unsigned u = __float_as_uint(sigmoid_precise(x));
    if ((u >> 16) >= __ldg(&g_thr16[b])) {
        int HW = c_HW[lev];
        int k = rem / HW, cell = rem - k * HW;
        unsigned a = (unsigned)(c_off[lev] + cell * 3 + k);
        unsigned pos = atomicAdd(&g_s.cnt[b], 1u);
        if (pos < CAP)
            g_cand[b * CAP + pos] =
                ((unsigned long long)u << 32) | (unsigned long long)(0xFFFFFFFFu - a);
    }
}

// ---- K4: exact rank of each candidate == stable sort position ------------
__global__ void k_rank() {
    __shared__ unsigned long long sk[CAP];   // 32 KB (only first n used)
    int b = blockIdx.y;
    unsigned n = g_s.cnt[b]; if (n > CAP) n = CAP;
    int i0 = blockIdx.x * RCHUNK;
    if (i0 >= (int)n) return;                // uniform per block
    for (int i = threadIdx.x; i < (int)n; i += RCHUNK) sk[i] = g_cand[b * CAP + i];
    __syncthreads();
    int i = i0 + threadIdx.x;
    unsigned long long key = (i < (int)n) ? sk[i] : ~0ull;
    unsigned r = 0;
#pragma unroll 4
    for (int j = 0; j < (int)n; j++) r += (sk[j] > key);
    if (i < (int)n && r < TOPK) {
        g_selU[b * TOPK + r] = (unsigned)(key >> 32);
        g_selA[b * TOPK + r] = 0xFFFFFFFFu - (unsigned)(key & 0xFFFFFFFFull);
    }
}

// ---- K5: decode the selected 16x1000 boxes -------------------------------
__global__ void k_decode(const float* __restrict__ b0, const float* __restrict__ b1,
                         const float* __restrict__ b2, const float* __restrict__ b3,
                         const float* __restrict__ b4) {
    int i = blockIdx.x * 256 + threadIdx.x;
    if (i >= BATCH * TOPK) return;
    int b = i / TOPK;
    int a = (int)g_selA[i];
    float score = __uint_as_float(g_selU[i]);
    int rem; int lev = level_of(a, rem);
    int cell = rem / 3, k = rem - cell * 3;
    int W = c_W[lev], HW = c_HW[lev];
    int hh = cell / W, ww = cell - hh * W;
    float st = c_stride[lev], sz = c_size[lev];
    float acx = ((float)ww + 0.5f) * st;
    float acy = ((float)hh + 0.5f) * st;
    float ratio = (k == 0) ? 0.5f : (k == 1) ? 1.0f : 2.0f;
    float sr = __fsqrt_rn(ratio);
    float aw = __fdiv_rn(sz, sr);
    float ah = sz * sr;
    const float* bp = (lev == 0) ? b0 : (lev == 1) ? b1 : (lev == 2) ? b2 : (lev == 3) ? b3 : b4;
    size_t base = (size_t)b * 12 * HW + (size_t)k * 4 * HW + cell;
    float d0 = bp[base], d1 = bp[base + HW], d2 = bp[base + 2 * (size_t)HW], d3 = bp[base + 3 * (size_t)HW];
    float cx = acx + d0 * aw;
    float cy = acy + d1 * ah;
    float w  = aw * expf(fminf(fmaxf(d2, -4.0f), 4.0f));
    float h  = ah * expf(fminf(fmaxf(d3, -4.0f), 4.0f));
    g_cx[i] = cx; g_cy[i] = cy; g_w[i] = w; g_h[i] = h; g_sc[i] = score;
    float x1 = cx - w * 0.5f, y1 = cy - h * 0.5f;
    float x2 = cx + w * 0.5f, y2 = cy + h * 0.5f;
    g_bx1[i] = x1; g_by1[i] = y1; g_bx2[i] = x2; g_by2[i] = y2;
    g_ar[i] = (x2 - x1) * (y2 - y1);
}

// ---- K6: NMS suppression bitmask, j-chunked ------------------------------
// grid (8 i-chunks, 4 j-chunks, 16 images), block 128. Block (ic,jc,b) writes
// words [8*jc, 8*jc+8) of rows [128*ic, 128*ic+128). Words partition by j:
// full coverage, no overlap, no atomics; zeros for j<=i come out naturally.
__global__ void k_mask() {
    __shared__ float sx1[256], sy1[256], sx2[256], sy2[256], sar[256];
    int jc = blockIdx.y, b = blockIdx.z;
    int jbase = jc * 256;
    for (int t = threadIdx.x; t < 256; t += 128) {
        int j = jbase + t;
        if (j < TOPK) {
            int g = b * TOPK + j;
            sx1[t] = g_bx1[g]; sy1[t] = g_by1[g];
            sx2[t] = g_bx2[g]; sy2[t] = g_by2[g];
            sar[t] = g_ar[g];
        } else {
            sx1[t] = 0.f; sy1[t] = 0.f; sx2[t] = 0.f; sy2[t] = 0.f; sar[t] = 0.f;
        }
    }
    __syncthreads();
    int i = blockIdx.x * 128 + threadIdx.x;
    if (i >= TOPK) return;
    int g = b * TOPK + i;
    float x1 = g_bx1[g], y1 = g_by1[g], x2 = g_bx2[g], y2 = g_by2[g], ar = g_ar[g];
    unsigned* out = &g_mask[((size_t)b * TOPK + i) * 32 + jc * 8];
#pragma unroll
    for (int w8 = 0; w8 < 8; w8++) {
        unsigned bits = 0;
#pragma unroll
        for (int jj = 0; jj < 32; jj++) {
            int tj = w8 * 32 + jj;
            int j = jbase + tj;
            if (j > i && j < TOPK) {
                float iw = fmaxf(fminf(x2, sx2[tj]) - fmaxf(x1, sx1[tj]), 0.0f);
                float ih = fmaxf(fminf(y2, sy2[tj]) - fmaxf(y1, sy1[tj]), 0.0f);
                float inter = iw * ih;
                float iou = inter / (ar + sar[tj] - inter + 1e-6f);
                if (iou > 0.7f) bits |= (1u << jj);
            }
        }
        out[w8] = bits;
    }
}

// ---- K7: fused greedy-NMS reduce + scatter (one block per image) ---------
__global__ void k_reduce_scatter(float* __restrict__ out, float* __restrict__ keepF) {
    extern __shared__ unsigned shm[];        // TOPK*32 words = 128000 B
    __shared__ unsigned s_keep[32];
    int b = blockIdx.x, tid = threadIdx.x;   // 1024 threads
    const unsigned* m = g_mask + (size_t)b * TOPK * 32;
    for (int i = tid; i < TOPK * 32; i += 1024) shm[i] = m[i];
    __syncthreads();
    if (tid < 32) {
        int lane = tid;
        unsigned remv = 0;                   // lane l: suppressed bits of boxes [32l,32l+31]
#pragma unroll 1
        for (int w = 0; w < 32; w++) {
            int rows = TOPK - w * 32; if (rows > 32) rows = 32;
            unsigned cur = __shfl_sync(0xffffffffu, remv, w);
            unsigned nr = 0;
#pragma unroll 1
            for (int rb = 0; rb < 32; rb += 8) {
                unsigned mwv[8], mcv[8];
#pragma unroll
                for (int r = 0; r < 8; r++) {
                    int i = w * 32 + rb + r;
                    bool vld = (rb + r) < rows;
                    mwv[r] = vld ? shm[i * 32 + w]    : 0u;   // diagonal word (broadcast)
                    mcv[r] = vld ? shm[i * 32 + lane] : 0u;   // per-lane column word
                }
#pragma unroll
                for (int r = 0; r < 8; r++) {
                    if (!((cur >> (rb + r)) & 1u)) {          // box kept
                        cur |= mwv[r];                        // forward bits only (j>i)
                        nr  |= mcv[r];
                    }
                }
            }
            remv |= nr;
        }
        s_keep[lane] = ~remv;
    }
    __syncthreads();
    for (int t = tid; t < TOPK; t += 1024) {
        if (!((s_keep[t >> 5] >> (t & 31)) & 1u)) continue;
        int i = b * TOPK + t;
        size_t base = (size_t)b * NANCH + g_selA[i];
        float* o = out + base * 5;
        o[0] = g_cx[i]; o[1] = g_cy[i]; o[2] = g_w[i]; o[3] = g_h[i]; o[4] = g_sc[i];
        if (keepF) keepF[base] = 1.0f;
    }
}

// ---- launch --------------------------------------------------------------
extern "C" void kernel_launch(void* const* d_in, const int* in_sizes, int n_in,
                              void* d_out, int out_size) {
    if (n_in < 10) return;
    const float* cls[5]; const float* bbx[5];
    if (in_sizes[1] == 786432) {     // grouped: cls_p2..p6, bbox_p2..p6
        for (int l = 0; l < 5; l++) { cls[l] = (const float*)d_in[l]; bbx[l] = (const float*)d_in[5 + l]; }
    } else {                         // interleaved
        for (int l = 0; l < 5; l++) { cls[l] = (const float*)d_in[2 * l]; bbx[l] = (const float*)d_in[2 * l + 1]; }
    }

    void* pS = nullptr;
    cudaGetSymbolAddress(&pS, g_s);
    cudaFuncSetAttribute(k_reduce_scatter, cudaFuncAttributeMaxDynamicSharedMemorySize, TOPK * 32 * 4);

    cudaMemsetAsync(pS, 0, sizeof(Scratch), 0);
    cudaMemsetAsync(d_out, 0, (size_t)out_size * sizeof(float), 0);

    const long long BA = (long long)BATCH * NANCH;
    float* keepF = nullptr;
    if ((long long)out_size >= BA * 6) keepF = (float*)d_out + BA * 5;

    // three no-op launches shift the ncu capture slot (-s 5 -c 1) onto the
    // sigmoid/histogram pass, which has never been profiled
    k_nop<<<1, 32>>>();
    k_nop<<<1, 32>>>();
    k_nop<<<1, 32>>>();

    int nba = (BATCH * NANCH + 255) / 256;   // 16368
    k_keys<<<nba, 256>>>(cls[0], cls[1], cls[2], cls[3], cls[4]);
    k_thr<<<BATCH, 1024>>>();
    k_compact<<<nba, 256>>>(cls[0], cls[1], cls[2], cls[3], cls[4]);
    k_rank<<<dim3(CAP / RCHUNK, BATCH), RCHUNK>>>();
    k_decode<<<(BATCH * TOPK + 255) / 256, 256>>>(bbx[0], bbx[1], bbx[2], bbx[3], bbx[4]);
    k_mask<<<dim3(8, 4, BATCH), 128>>>();
    k_reduce_scatter<<<BATCH, 1024, TOPK * 32 * 4>>>((float*)d_out, keepF);
}

// round 7
// speedup vs baseline: 3.0570x; 1.9336x over previous
#include <cuda_runtime.h>
#include <stdint.h>

#define BATCH   16
#define NANCH   261888          // 3 * (65536+16384+4096+1024+256)
#define TOPK    1000
#define CAP     4096            // candidate capacity (expected ~2500 at 13-bit bins)
#define NBINS   8192            // 13-bit histogram (fits 32 KB smem)
#define BSHIFT  19              // u >> 19 -> 13-bit bin
#define NLEV    5
#define RCHUNK  256             // k_rank rows per block
#define KBLK    16              // histogram blocks per image

// ---- static level tables -------------------------------------------------
__constant__ int   c_HW[NLEV]     = {65536, 16384, 4096, 1024, 256};
__constant__ int   c_W[NLEV]      = {256, 128, 64, 32, 16};
__constant__ float c_stride[NLEV] = {4.f, 8.f, 16.f, 32.f, 64.f};
__constant__ float c_size[NLEV]   = {32.f, 64.f, 128.f, 256.f, 512.f};
__constant__ int   c_off[NLEV]    = {0, 196608, 245760, 258048, 261120};

__device__ __forceinline__ int level_of(int j, int& rem) {
    if (j < 196608) { rem = j;          return 0; }
    if (j < 245760) { rem = j - 196608; return 1; }
    if (j < 258048) { rem = j - 245760; return 2; }
    if (j < 261120) { rem = j - 258048; return 3; }
    rem = j - 261120; return 4;
}

// ---- scratch (static device globals; no allocation anywhere) -------------
struct Scratch { unsigned hist[BATCH * NBINS]; unsigned cnt[BATCH]; };
static __device__ Scratch            g_s;          // zeroed by ONE memset
static __device__ unsigned int       g_thr13[BATCH];
static __device__ unsigned long long g_cand[BATCH * CAP];
static __device__ unsigned int       g_selA[BATCH * TOPK];
static __device__ unsigned int       g_selU[BATCH * TOPK];
static __device__ float g_cx[BATCH*TOPK], g_cy[BATCH*TOPK], g_w[BATCH*TOPK], g_h[BATCH*TOPK];
static __device__ float g_sc[BATCH*TOPK];
static __device__ float g_bx1[BATCH*TOPK], g_by1[BATCH*TOPK], g_bx2[BATCH*TOPK], g_by2[BATCH*TOPK];
static __device__ float g_ar[BATCH*TOPK];
static __device__ unsigned int       g_mask[BATCH * TOPK * 32];

// precise sigmoid matching XLA logistic expansion: 1 / (1 + exp(-x))
__device__ __forceinline__ float sigmoid_precise(float x) {
    return __fdiv_rn(1.0f, __fadd_rn(1.0f, expf(-x)));
}

// ---- dummy: keeps the ncu capture slot on k_keys -------------------------
__global__ void k_nop() {}

// ---- K1: sigmoid -> 13-bit histogram, SMEM-privatized, float4 loads ------
// grid (KBLK, BATCH), block 1024. All 4 lanes of a float4 share a level
// (every level boundary is divisible by 4).
__global__ void k_keys(const float* __restrict__ c0, const float* __restrict__ c1,
                       const float* __restrict__ c2, const float* __restrict__ c3,
                       const float* __restrict__ c4) {
    __shared__ unsigned sh[NBINS];   // 32 KB
    int b = blockIdx.y;
    for (int i = threadIdx.x; i < NBINS; i += 1024) sh[i] = 0;
    __syncthreads();
    const int F4 = NANCH / 4;                      // 65472 float4 per image
    const int per = (F4 + KBLK - 1) / KBLK;        // 4092
    int start = blockIdx.x * per;
    int end = start + per; if (end > F4) end = F4;
    for (int f = start + threadIdx.x; f < end; f += 1024) {
        int j = f * 4;
        int rem; int lev = level_of(j, rem);
        const float* p = (lev == 0) ? c0 : (lev == 1) ? c1 : (lev == 2) ? c2 : (lev == 3) ? c3 : c4;
        float4 v = ((const float4*)p)[((size_t)b * 3 * c_HW[lev] + rem) >> 2];
        atomicAdd(&sh[__float_as_uint(sigmoid_precise(v.x)) >> BSHIFT], 1u);
        atomicAdd(&sh[__float_as_uint(sigmoid_precise(v.y)) >> BSHIFT], 1u);
        atomicAdd(&sh[__float_as_uint(sigmoid_precise(v.z)) >> BSHIFT], 1u);
        atomicAdd(&sh[__float_as_uint(sigmoid_precise(v.w)) >> BSHIFT], 1u);
    }
    __syncthreads();
    for (int i = threadIdx.x; i < NBINS; i += 1024) {
        unsigned v = sh[i];
        if (v) atomicAdd(&g_s.hist[b * NBINS + i], v);
    }
}

// ---- K2: fully parallel per-image 13-bit threshold -----------------------
// thr = max t with count(u>>BSHIFT >= t) >= TOPK
__global__ void k_thr() {
    __shared__ unsigned s_val[1024];
    __shared__ int s_chunk;
    __shared__ unsigned s_above;
    __shared__ unsigned s_bin[8];
    int b = blockIdx.x, t = threadIdx.x;   // 1024 threads; 8 bins per thread
    const unsigned* h = g_s.hist + b * NBINS;
    const uint4* h4 = (const uint4*)h;
    uint4 a0 = h4[t * 2], a1 = h4[t * 2 + 1];
    unsigned s = a0.x + a0.y + a0.z + a0.w + a1.x + a1.y + a1.z + a1.w;
    unsigned v = s;
    for (int off = 1; off < 1024; off <<= 1) {
        s_val[t] = v;
        __syncthreads();
        unsigned add = (t + off < 1024) ? s_val[t + off] : 0u;
        __syncthreads();
        v += add;
    }
    s_val[t] = v;
    __syncthreads();
    if (v >= TOPK && (t == 1023 || s_val[t + 1] < TOPK)) {
        s_chunk = t;
        s_above = (t == 1023) ? 0u : s_val[t + 1];
    }
    __syncthreads();
    int c = s_chunk;
    unsigned above = s_above;
    if (t < 8) s_bin[t] = h[c * 8 + t];
    __syncthreads();
    if (t < 8) {
        unsigned suf = 0;
        for (int j = 7; j >= t; j--) suf += s_bin[j];
        unsigned sufnext = suf - s_bin[t];
        if (above + suf >= TOPK && above + sufnext < TOPK)
            g_thr13[b] = (unsigned)(c * 8 + t);
    }
}

// ---- K3: compact candidates (key64 = score_bits<<32 | ~anchor_index) -----
// grid (KBLK, BATCH), block 1024, float4 loads
__global__ void k_compact(const float* __restrict__ c0, const float* __restrict__ c1,
                          const float* __restrict__ c2, const float* __restrict__ c3,
                          const float* __restrict__ c4) {
    int b = blockIdx.y;
    unsigned thr = __ldg(&g_thr13[b]);
    const int F4 = NANCH / 4;
    const int per = (F4 + KBLK - 1) / KBLK;
    int start = blockIdx.x * per;
    int end = start + per; if (end > F4) end = F4;
    for (int f = start + threadIdx.x; f < end; f += 1024) {
        int j = f * 4;
        int rem; int lev = level_of(j, rem);
        const float* p = (lev == 0) ? c0 : (lev == 1) ? c1 : (lev == 2) ? c2 : (lev == 3) ? c3 : c4;
        float4 v = ((const float4*)p)[((size_t)b * 3 * c_HW[lev] + rem) >> 2];
        int HW = c_HW[lev];
        float xs[4] = {v.x, v.y, v.z, v.w};
#pragma unroll
        for (int e = 0; e < 4; e++) {
            unsigned u = __float_as_uint(sigmoid_precise(xs[e]));
            if ((u >> BSHIFT) >= thr) {
                int re = rem + e;
                int k = re / HW, cell = re - k * HW;
                unsigned a = (unsigned)(c_off[lev] + cell * 3 + k);
                unsigned pos = atomicAdd(&g_s.cnt[b], 1u);
                if (pos < CAP)
                    g_cand[b * CAP + pos] =
                        ((unsigned long long)u << 32) | (unsigned long long)(0xFFFFFFFFu - a);
            }
        }
    }
}

// ---- K4: exact rank of each candidate == stable sort position ------------
__global__ void k_rank() {
    __shared__ unsigned long long sk[CAP];   // 32 KB (only first n used)
    int b = blockIdx.y;
    unsigned n = g_s.cnt[b]; if (n > CAP) n = CAP;
    int i0 = blockIdx.x * RCHUNK;
    if (i0 >= (int)n) return;                // uniform per block
    for (int i = threadIdx.x; i < (int)n; i += RCHUNK) sk[i] = g_cand[b * CAP + i];
    __syncthreads();
    int i = i0 + threadIdx.x;
    unsigned long long key = (i < (int)n) ? sk[i] : ~0ull;
    unsigned r = 0;
#pragma unroll 4
    for (int j = 0; j < (int)n; j++) r += (sk[j] > key);
    if (i < (int)n && r < TOPK) {
        g_selU[b * TOPK + r] = (unsigned)(key >> 32);
        g_selA[b * TOPK + r] = 0xFFFFFFFFu - (unsigned)(key & 0xFFFFFFFFull);
    }
}

// ---- K5: decode the selected 16x1000 boxes -------------------------------
__global__ void k_decode(const float* __restrict__ b0, const float* __restrict__ b1,
                         const float* __restrict__ b2, const float* __restrict__ b3,
                         const float* __restrict__ b4) {
    int i = blockIdx.x * 256 + threadIdx.x;
    if (i >= BATCH * TOPK) return;
    int b = i / TOPK;
    int a = (int)g_selA[i];
    float score = __uint_as_float(g_selU[i]);
    int rem; int lev = level_of(a, rem);
    int cell = rem / 3, k = rem - cell * 3;
    int W = c_W[lev], HW = c_HW[lev];
    int hh = cell / W, ww = cell - hh * W;
    float st = c_stride[lev], sz = c_size[lev];
    float acx = ((float)ww + 0.5f) * st;
    float acy = ((float)hh + 0.5f) * st;
    float ratio = (k == 0) ? 0.5f : (k == 1) ? 1.0f : 2.0f;
    float sr = __fsqrt_rn(ratio);
    float aw = __fdiv_rn(sz, sr);
    float ah = sz * sr;
    const float* bp = (lev == 0) ? b0 : (lev == 1) ? b1 : (lev == 2) ? b2 : (lev == 3) ? b3 : b4;
    size_t base = (size_t)b * 12 * HW + (size_t)k * 4 * HW + cell;
    float d0 = bp[base], d1 = bp[base + HW], d2 = bp[base + 2 * (size_t)HW], d3 = bp[base + 3 * (size_t)HW];
    float cx = acx + d0 * aw;
    float cy = acy + d1 * ah;
    float w  = aw * expf(fminf(fmaxf(d2, -4.0f), 4.0f));
    float h  = ah * expf(fminf(fmaxf(d3, -4.0f), 4.0f));
    g_cx[i] = cx; g_cy[i] = cy; g_w[i] = w; g_h[i] = h; g_sc[i] = score;
    float x1 = cx - w * 0.5f, y1 = cy - h * 0.5f;
    float x2 = cx + w * 0.5f, y2 = cy + h * 0.5f;
    g_bx1[i] = x1; g_by1[i] = y1; g_bx2[i] = x2; g_by2[i] = y2;
    g_ar[i] = (x2 - x1) * (y2 - y1);
}

// ---- K6: NMS suppression bitmask, j-chunked ------------------------------
__global__ void k_mask() {
    __shared__ float sx1[256], sy1[256], sx2[256], sy2[256], sar[256];
    int jc = blockIdx.y, b = blockIdx.z;
    int jbase = jc * 256;
    for (int t = threadIdx.x; t < 256; t += 128) {
        int j = jbase + t;
        if (j < TOPK) {
            int g = b * TOPK + j;
            sx1[t] = g_bx1[g]; sy1[t] = g_by1[g];
            sx2[t] = g_bx2[g]; sy2[t] = g_by2[g];
            sar[t] = g_ar[g];
        } else {
            sx1[t] = 0.f; sy1[t] = 0.f; sx2[t] = 0.f; sy2[t] = 0.f; sar[t] = 0.f;
        }
    }
    __syncthreads();
    int i = blockIdx.x * 128 + threadIdx.x;
    if (i >= TOPK) return;
    int g = b * TOPK + i;
    float x1 = g_bx1[g], y1 = g_by1[g], x2 = g_bx2[g], y2 = g_by2[g], ar = g_ar[g];
    unsigned* out = &g_mask[((size_t)b * TOPK + i) * 32 + jc * 8];
#pragma unroll
    for (int w8 = 0; w8 < 8; w8++) {
        unsigned bits = 0;
#pragma unroll
        for (int jj = 0; jj < 32; jj++) {
            int tj = w8 * 32 + jj;
            int j = jbase + tj;
            if (j > i && j < TOPK) {
                float iw = fmaxf(fminf(x2, sx2[tj]) - fmaxf(x1, sx1[tj]), 0.0f);
                float ih = fmaxf(fminf(y2, sy2[tj]) - fmaxf(y1, sy1[tj]), 0.0f);
                float inter = iw * ih;
                float iou = inter / (ar + sar[tj] - inter + 1e-6f);
                if (iou > 0.7f) bits |= (1u << jj);
            }
        }
        out[w8] = bits;
    }
}

// ---- K7: fused greedy-NMS reduce + scatter (one block per image) ---------
__global__ void k_reduce_scatter(float* __restrict__ out, float* __restrict__ keepF) {
    extern __shared__ unsigned shm[];        // TOPK*32 words = 128000 B
    __shared__ unsigned s_keep[32];
    int b = blockIdx.x, tid = threadIdx.x;   // 1024 threads
    const unsigned* m = g_mask + (size_t)b * TOPK * 32;
    for (int i = tid; i < TOPK * 32; i += 1024) shm[i] = m[i];
    __syncthreads();
    if (tid < 32) {
        int lane = tid;
        unsigned remv = 0;                   // lane l: suppressed bits of boxes [32l,32l+31]
#pragma unroll 1
        for (int w = 0; w < 32; w++) {
            int rows = TOPK - w * 32; if (rows > 32) rows = 32;
            unsigned cur = __shfl_sync(0xffffffffu, remv, w);
            unsigned nr = 0;
#pragma unroll 1
            for (int rb = 0; rb < 32; rb += 8) {
                unsigned mwv[8], mcv[8];
#pragma unroll
                for (int r = 0; r < 8; r++) {
                    int i = w * 32 + rb + r;
                    bool vld = (rb + r) < rows;
                    mwv[r] = vld ? shm[i * 32 + w]    : 0u;   // diagonal word (broadcast)
                    mcv[r] = vld ? shm[i * 32 + lane] : 0u;   // per-lane column word
                }
#pragma unroll
                for (int r = 0; r < 8; r++) {
                    if (!((cur >> (rb + r)) & 1u)) {          // box kept
                        cur |= mwv[r];                        // forward bits only (j>i)
                        nr  |= mcv[r];
                    }
                }
            }
            remv |= nr;
        }
        s_keep[lane] = ~remv;
    }
    __syncthreads();
    for (int t = tid; t < TOPK; t += 1024) {
        if (!((s_keep[t >> 5] >> (t & 31)) & 1u)) continue;
        int i = b * TOPK + t;
        size_t base = (size_t)b * NANCH + g_selA[i];
        float* o = out + base * 5;
        o[0] = g_cx[i]; o[1] = g_cy[i]; o[2] = g_w[i]; o[3] = g_h[i]; o[4] = g_sc[i];
        if (keepF) keepF[base] = 1.0f;
    }
}

// ---- launch --------------------------------------------------------------
extern "C" void kernel_launch(void* const* d_in, const int* in_sizes, int n_in,
                              void* d_out, int out_size) {
    if (n_in < 10) return;
    const float* cls[5]; const float* bbx[5];
    if (in_sizes[1] == 786432) {     // grouped: cls_p2..p6, bbox_p2..p6
        for (int l = 0; l < 5; l++) { cls[l] = (const float*)d_in[l]; bbx[l] = (const float*)d_in[5 + l]; }
    } else {                         // interleaved
        for (int l = 0; l < 5; l++) { cls[l] = (const float*)d_in[2 * l]; bbx[l] = (const float*)d_in[2 * l + 1]; }
    }

    void* pS = nullptr;
    cudaGetSymbolAddress(&pS, g_s);
    cudaFuncSetAttribute(k_reduce_scatter, cudaFuncAttributeMaxDynamicSharedMemorySize, TOPK * 32 * 4);

    cudaMemsetAsync(pS, 0, sizeof(Scratch), 0);
    cudaMemsetAsync(d_out, 0, (size_t)out_size * sizeof(float), 0);

    const long long BA = (long long)BATCH * NANCH;
    float* keepF = nullptr;
    if ((long long)out_size >= BA * 6) keepF = (float*)d_out + BA * 5;

    // keep the ncu capture slot (-s 5 -c 1) on k_keys
    k_nop<<<1, 32>>>();
    k_nop<<<1, 32>>>();
    k_nop<<<1, 32>>>();

    k_keys<<<dim3(KBLK, BATCH), 1024>>>(cls[0], cls[1], cls[2], cls[3], cls[4]);
    k_thr<<<BATCH, 1024>>>();
    k_compact<<<dim3(KBLK, BATCH), 1024>>>(cls[0], cls[1], cls[2], cls[3], cls[4]);
    k_rank<<<dim3(CAP / RCHUNK, BATCH), RCHUNK>>>();
    k_decode<<<(BATCH * TOPK + 255) / 256, 256>>>(bbx[0], bbx[1], bbx[2], bbx[3], bbx[4]);
    k_mask<<<dim3(8, 4, BATCH), 128>>>();
    k_reduce_scatter<<<BATCH, 1024, TOPK * 32 * 4>>>((float*)d_out, keepF);
}